// round 6
// baseline (speedup 1.0000x reference)
#include <cuda_runtime.h>
#include <cuda_bf16.h>
#include <stdint.h>

#define B_   8
#define C_   256
#define HW   4096
#define OC3  768
#define GRPS 96

// Scratch (alloc-free rule: __device__ globals)
__device__ float g_qkv[B_ * OC3 * HW];   // ~100.7 MB
__device__ float g_agg[B_ * OC3 * HW];   // ~100.7 MB
__device__ float g_kv [B_ * 64 * 72];    // per (b,head) 8x9 kv matrix

// ===========================================================================
// mma.sync / ldmatrix helpers (sm_80+ — legal on compute_103)
// ===========================================================================
__device__ __forceinline__ uint32_t smem_u32(const void* p) {
    uint32_t a;
    asm("{ .reg .u64 t; cvta.to.shared.u64 t, %1; cvt.u32.u64 %0, t; }"
        : "=r"(a) : "l"(p));
    return a;
}
__device__ __forceinline__ void ldsm_x4(uint32_t& r0, uint32_t& r1,
                                        uint32_t& r2, uint32_t& r3, uint32_t addr) {
    asm volatile("ldmatrix.sync.aligned.m8n8.x4.shared.b16 {%0,%1,%2,%3}, [%4];"
        : "=r"(r0), "=r"(r1), "=r"(r2), "=r"(r3) : "r"(addr));
}
__device__ __forceinline__ void ldsm_x2t(uint32_t& r0, uint32_t& r1, uint32_t addr) {
    asm volatile("ldmatrix.sync.aligned.m8n8.x2.trans.shared.b16 {%0,%1}, [%2];"
        : "=r"(r0), "=r"(r1) : "r"(addr));
}
__device__ __forceinline__ void mma_bf16(float& c0, float& c1, float& c2, float& c3,
    uint32_t a0, uint32_t a1, uint32_t a2, uint32_t a3, uint32_t b0, uint32_t b1) {
    asm volatile("mma.sync.aligned.m16n8k16.row.col.f32.bf16.bf16.f32 "
        "{%0,%1,%2,%3}, {%4,%5,%6,%7}, {%8,%9}, {%0,%1,%2,%3};"
        : "+f"(c0), "+f"(c1), "+f"(c2), "+f"(c3)
        : "r"(a0), "r"(a1), "r"(a2), "r"(a3), "r"(b0), "r"(b1));
}

// bf16 2-way split of a float4 (hi + lo packed as 4 bf16 each)
__device__ __forceinline__ void split4(float4 v, uint2& hi, uint2& lo) {
    __nv_bfloat162 h0 = __floats2bfloat162_rn(v.x, v.y);
    __nv_bfloat162 h1 = __floats2bfloat162_rn(v.z, v.w);
    float2 f0 = __bfloat1622float2(h0);
    float2 f1 = __bfloat1622float2(h1);
    __nv_bfloat162 l0 = __floats2bfloat162_rn(v.x - f0.x, v.y - f0.y);
    __nv_bfloat162 l1 = __floats2bfloat162_rn(v.z - f1.x, v.w - f1.y);
    hi = make_uint2(*(uint32_t*)&h0, *(uint32_t*)&h1);
    lo = make_uint2(*(uint32_t*)&l0, *(uint32_t*)&l1);
}

// ---------------------------------------------------------------------------
// K1 (HMMA): qkv[b,m,n] = sum_k w[m,k] * x[b,k,n]
// CTA 128x128, 8 warps (2x4 -> 64x32 warp tiles), BK=32, 3-pass bf16 split.
// A smem [m][k] pad 40; B smem [k][n] pad 136 (ldmatrix.x2.trans).
// ---------------------------------------------------------------------------
#define K1_LDA 40
#define K1_LDB 136

__global__ __launch_bounds__(256) void qkv_mma_k(const float* __restrict__ x,
                                                 const float* __restrict__ w)
{
    __shared__ __nv_bfloat16 sA[2][128 * K1_LDA];   // hi, lo
    __shared__ __nv_bfloat16 sB[2][32 * K1_LDB];

    int tid = threadIdx.x, lane = tid & 31, wrp = tid >> 5;
    int b = blockIdx.z, n0 = blockIdx.x * 128, m0 = blockIdx.y * 128;
    const float* xb = x + (size_t)b * C_ * HW;
    float* ob = g_qkv + (size_t)b * OC3 * HW;

    int wm = (wrp >> 2) * 64, wn = (wrp & 3) * 32;
    float acc[4][4][4] = {};

    uint32_t aHi = smem_u32(&sA[0][0]), aLo = smem_u32(&sA[1][0]);
    uint32_t bHi = smem_u32(&sB[0][0]), bLo = smem_u32(&sB[1][0]);

    for (int kc = 0; kc < 8; kc++) {
        __syncthreads();
        #pragma unroll
        for (int i = 0; i < 4; i++) {               // A: 128x32 fp32
            int f4 = i * 256 + tid, m = f4 >> 3, k4 = f4 & 7;
            float4 v = *(const float4*)(w + (size_t)(m0 + m) * C_ + kc * 32 + k4 * 4);
            uint2 hp, lp; split4(v, hp, lp);
            *(uint2*)&sA[0][m * K1_LDA + k4 * 4] = hp;
            *(uint2*)&sA[1][m * K1_LDA + k4 * 4] = lp;
        }
        #pragma unroll
        for (int i = 0; i < 4; i++) {               // B: 32x128 fp32
            int f4 = i * 256 + tid, k = f4 >> 5, nn = f4 & 31;
            float4 v = *(const float4*)(xb + (size_t)(kc * 32 + k) * HW + n0 + nn * 4);
            uint2 hp, lp; split4(v, hp, lp);
            *(uint2*)&sB[0][k * K1_LDB + nn * 4] = hp;
            *(uint2*)&sB[1][k * K1_LDB + nn * 4] = lp;
        }
        __syncthreads();

        #pragma unroll
        for (int pass = 0; pass < 3; pass++) {
            uint32_t aB = (pass == 2) ? aLo : aHi;
            uint32_t bB = (pass == 1) ? bLo : bHi;
            #pragma unroll
            for (int ks = 0; ks < 2; ks++) {
                uint32_t af[4][4], bf[4][2];
                #pragma unroll
                for (int mi = 0; mi < 4; mi++)
                    ldsm_x4(af[mi][0], af[mi][1], af[mi][2], af[mi][3],
                        aB + (uint32_t)(((wm + mi * 16 + (lane & 15)) * K1_LDA
                                         + ks * 16 + (lane >> 4) * 8) * 2));
                #pragma unroll
                for (int ni = 0; ni < 4; ni++)
                    ldsm_x2t(bf[ni][0], bf[ni][1],
                        bB + (uint32_t)(((ks * 16 + (lane & 15)) * K1_LDB
                                         + wn + ni * 8) * 2));
                #pragma unroll
                for (int mi = 0; mi < 4; mi++)
                    #pragma unroll
                    for (int ni = 0; ni < 4; ni++)
                        mma_bf16(acc[mi][ni][0], acc[mi][ni][1],
                                 acc[mi][ni][2], acc[mi][ni][3],
                                 af[mi][0], af[mi][1], af[mi][2], af[mi][3],
                                 bf[ni][0], bf[ni][1]);
            }
        }
    }
    #pragma unroll
    for (int mi = 0; mi < 4; mi++) {
        int mr = m0 + wm + mi * 16 + (lane >> 2);
        #pragma unroll
        for (int ni = 0; ni < 4; ni++) {
            int n = n0 + wn + ni * 8 + (lane & 3) * 2;
            *(float2*)(ob + (size_t)mr * HW + n) =
                make_float2(acc[mi][ni][0], acc[mi][ni][1]);
            *(float2*)(ob + (size_t)(mr + 8) * HW + n) =
                make_float2(acc[mi][ni][2], acc[mi][ni][3]);
        }
    }
}

// ---------------------------------------------------------------------------
// K2: fused depthwise 5x5 (pad 2) + grouped 8x8 pointwise. (unchanged)
// ---------------------------------------------------------------------------
__global__ __launch_bounds__(256) void dw_agg_k(const float* __restrict__ wdw,
                                                const float* __restrict__ wpw)
{
    int bg = blockIdx.z;
    int b = bg / GRPS, g = bg % GRPS;
    int y0 = blockIdx.y * 32, x0 = blockIdx.x * 32;

    __shared__ float s[8][36][36];
    __shared__ float swd[8][25];
    __shared__ float swp[64];
    int tid = threadIdx.x;

    if (tid < 200) swd[tid / 25][tid % 25] = wdw[(size_t)(g * 8 + tid / 25) * 25 + tid % 25];
    if (tid < 64)  swp[tid] = wpw[(size_t)g * 64 + tid];

    const float* src = g_qkv + ((size_t)b * OC3 + g * 8) * HW;
    for (int i = tid; i < 8 * 36 * 36; i += 256) {
        int ch = i / 1296, r = (i % 1296) / 36, c = i % 36;
        int y = y0 + r - 2, x = x0 + c - 2;
        float v = 0.f;
        if ((unsigned)y < 64u && (unsigned)x < 64u) v = src[(size_t)ch * HW + y * 64 + x];
        s[ch][r][c] = v;
    }
    __syncthreads();

    float* dst = g_agg + ((size_t)b * OC3 + g * 8) * HW;
    for (int p = tid; p < 1024; p += 256) {
        int py = p >> 5, px = p & 31;
        float dwv[8];
        #pragma unroll
        for (int ch = 0; ch < 8; ch++) {
            float a = 0.f;
            #pragma unroll
            for (int dy = 0; dy < 5; dy++)
                #pragma unroll
                for (int dx = 0; dx < 5; dx++)
                    a = fmaf(s[ch][py + dy][px + dx], swd[ch][dy * 5 + dx], a);
            dwv[ch] = a;
        }
        int off = (y0 + py) * 64 + x0 + px;
        #pragma unroll
        for (int o = 0; o < 8; o++) {
            float a = 0.f;
            #pragma unroll
            for (int i2 = 0; i2 < 8; i2++) a = fmaf(swp[o * 8 + i2], dwv[i2], a);
            dst[(size_t)o * HW + off] = a;
        }
    }
}

// ---------------------------------------------------------------------------
// K3: kv reduction (unchanged)
// ---------------------------------------------------------------------------
__global__ __launch_bounds__(256) void kv_k()
{
    int bh = blockIdx.x;
    int b = bh >> 6, h = bh & 63;
    const float* base = (h < 32 ? g_qkv : g_agg) + ((size_t)b * OC3 + (h & 31) * 24) * HW;
    const float* kp = base + 8 * HW;
    const float* vp = base + 16 * HW;

    float acc[8][9] = {};
    for (int n = threadIdx.x; n < HW; n += 256) {
        float kr[8], vr[8];
        #pragma unroll
        for (int d = 0; d < 8; d++) {
            kr[d] = fmaxf(kp[(size_t)d * HW + n], 0.f);
            vr[d] = vp[(size_t)d * HW + n];
        }
        #pragma unroll
        for (int d = 0; d < 8; d++) {
            #pragma unroll
            for (int e = 0; e < 8; e++) acc[d][e] = fmaf(kr[d], vr[e], acc[d][e]);
            acc[d][8] += kr[d];
        }
    }
    __shared__ float sred[8][72];
    int w = threadIdx.x >> 5, lane = threadIdx.x & 31;
    #pragma unroll
    for (int d = 0; d < 8; d++)
        #pragma unroll
        for (int e = 0; e < 9; e++) {
            float v = acc[d][e];
            #pragma unroll
            for (int o = 16; o > 0; o >>= 1) v += __shfl_down_sync(0xffffffffu, v, o);
            if (lane == 0) sred[w][d * 9 + e] = v;
        }
    __syncthreads();
    if (threadIdx.x < 72) {
        float v = 0.f;
        #pragma unroll
        for (int w2 = 0; w2 < 8; w2++) v += sred[w2][threadIdx.x];
        g_kv[(size_t)bh * 72 + threadIdx.x] = v;
    }
}

// ---------------------------------------------------------------------------
// K4 (HMMA): fused attention + proj GEMM + BN + residual.
// out[b,o,n] = x[b,o,n] + BN( sum_c wproj[o,c] * att[b,c,n] )
// att generated on-the-fly per 8-head chunk (64 k-values), split to bf16
// hi/lo at generation; same 3-pass HMMA core as K1. BK=64, 8 chunks.
// ---------------------------------------------------------------------------
#define K4_LDA 72
#define K4_LDB 136
#define K4_SM_KV   0
#define K4_SM_A    18432                 // 4608 floats
#define K4_SM_B    (18432 + 36864)       // + 2*128*72*2
#define K4_SM_TOT  (18432 + 36864 + 34816)   // 90112 B

__global__ __launch_bounds__(256) void att_proj_mma_k(const float* __restrict__ wproj,
    const float* __restrict__ x, const float* __restrict__ gamma,
    const float* __restrict__ beta, const float* __restrict__ mean,
    const float* __restrict__ var, float* __restrict__ out)
{
    extern __shared__ char smc[];
    float* kv_s = (float*)(smc + K4_SM_KV);                  // 64*72
    __nv_bfloat16* sA = (__nv_bfloat16*)(smc + K4_SM_A);     // [2][128*72]
    __nv_bfloat16* sB = (__nv_bfloat16*)(smc + K4_SM_B);     // [2][64*136]

    int tid = threadIdx.x, lane = tid & 31, wrp = tid >> 5;
    int b = blockIdx.z, n0 = blockIdx.x * 128, m0 = blockIdx.y * 128;
    int wm = (wrp >> 2) * 64, wn = (wrp & 3) * 32;
    int nl = tid & 127, hb = tid >> 7;

    for (int i = tid; i < 4608; i += 256) kv_s[i] = g_kv[(size_t)b * 4608 + i];

    float acc[4][4][4] = {};
    uint32_t aHi = smem_u32(sA), aLo = aHi + 128 * K4_LDA * 2;
    uint32_t bHi = smem_u32(sB), bLo = bHi + 64 * K4_LDB * 2;
    __nv_bfloat16* sAlo = sA + 128 * K4_LDA;
    __nv_bfloat16* sBlo = sB + 64 * K4_LDB;

    __syncthreads();

    for (int hc = 0; hc < 8; hc++) {
        if (hc) __syncthreads();
        // ---- stage W chunk: [m][k], 128x64 fp32 ----
        #pragma unroll
        for (int i = 0; i < 8; i++) {
            int f4 = i * 256 + tid, m = f4 >> 4, k4 = f4 & 15;
            float4 v = *(const float4*)(wproj + (size_t)(m0 + m) * 512 + hc * 64 + k4 * 4);
            uint2 hp, lp; split4(v, hp, lp);
            *(uint2*)&sA  [m * K4_LDA + k4 * 4] = hp;
            *(uint2*)&sAlo[m * K4_LDA + k4 * 4] = lp;
        }
        // ---- generate att chunk: 8 heads x 128 tokens -> [k][n] hi/lo ----
        #pragma unroll
        for (int i = 0; i < 4; i++) {
            int hl = hb + i * 2;
            int h = hc * 8 + hl;
            const float* src = (h < 32 ? g_qkv : g_agg)
                             + ((size_t)b * OC3 + (h & 31) * 24) * HW + n0 + nl;
            float q[8];
            #pragma unroll
            for (int d = 0; d < 8; d++) q[d] = fmaxf(src[(size_t)d * HW], 0.f);
            const float* kvh = kv_s + h * 72;
            float den = 0.f;
            #pragma unroll
            for (int d = 0; d < 8; d++) den = fmaf(q[d], kvh[d * 9 + 8], den);
            float inv = 1.f / (den + 1e-15f);
            #pragma unroll
            for (int e = 0; e < 8; e++) {
                float s = 0.f;
                #pragma unroll
                for (int d = 0; d < 8; d++) s = fmaf(q[d], kvh[d * 9 + e], s);
                s *= inv;
                __nv_bfloat16 hbv = __float2bfloat16(s);
                __nv_bfloat16 lbv = __float2bfloat16(s - __bfloat162float(hbv));
                int row = hl * 8 + e;
                sB  [row * K4_LDB + nl] = hbv;
                sBlo[row * K4_LDB + nl] = lbv;
            }
        }
        __syncthreads();

        #pragma unroll
        for (int pass = 0; pass < 3; pass++) {
            uint32_t aB = (pass == 2) ? aLo : aHi;
            uint32_t bB = (pass == 1) ? bLo : bHi;
            #pragma unroll
            for (int ks = 0; ks < 4; ks++) {
                uint32_t af[4][4], bf[4][2];
                #pragma unroll
                for (int mi = 0; mi < 4; mi++)
                    ldsm_x4(af[mi][0], af[mi][1], af[mi][2], af[mi][3],
                        aB + (uint32_t)(((wm + mi * 16 + (lane & 15)) * K4_LDA
                                         + ks * 16 + (lane >> 4) * 8) * 2));
                #pragma unroll
                for (int ni = 0; ni < 4; ni++)
                    ldsm_x2t(bf[ni][0], bf[ni][1],
                        bB + (uint32_t)(((ks * 16 + (lane & 15)) * K4_LDB
                                         + wn + ni * 8) * 2));
                #pragma unroll
                for (int mi = 0; mi < 4; mi++)
                    #pragma unroll
                    for (int ni = 0; ni < 4; ni++)
                        mma_bf16(acc[mi][ni][0], acc[mi][ni][1],
                                 acc[mi][ni][2], acc[mi][ni][3],
                                 af[mi][0], af[mi][1], af[mi][2], af[mi][3],
                                 bf[ni][0], bf[ni][1]);
            }
        }
    }

    // ---- epilogue: BN + residual ----
    #pragma unroll
    for (int mi = 0; mi < 4; mi++) {
        #pragma unroll
        for (int half = 0; half < 2; half++) {
            int o = m0 + wm + mi * 16 + (lane >> 2) + half * 8;
            float invg = gamma[o] / sqrtf(var[o] + 1e-6f);
            float bias = beta[o] - mean[o] * invg;
            #pragma unroll
            for (int ni = 0; ni < 4; ni++) {
                int n = n0 + wn + ni * 8 + (lane & 3) * 2;
                size_t off = ((size_t)b * C_ + o) * HW + n;
                float2 xv = *(const float2*)(x + off);
                float2 r;
                r.x = xv.x + acc[mi][ni][half * 2 + 0] * invg + bias;
                r.y = xv.y + acc[mi][ni][half * 2 + 1] * invg + bias;
                *(float2*)(out + off) = r;
            }
        }
    }
}

// ---------------------------------------------------------------------------
extern "C" void kernel_launch(void* const* d_in, const int* in_sizes, int n_in,
                              void* d_out, int out_size)
{
    const float* x     = (const float*)d_in[0];
    const float* wqkv  = (const float*)d_in[1];
    const float* wdw   = (const float*)d_in[2];
    const float* wpw   = (const float*)d_in[3];
    const float* wproj = (const float*)d_in[4];
    const float* gamma = (const float*)d_in[5];
    const float* beta  = (const float*)d_in[6];
    const float* mean  = (const float*)d_in[7];
    const float* var   = (const float*)d_in[8];
    float* out = (float*)d_out;

    qkv_mma_k<<<dim3(32, 6, 8), 256>>>(x, wqkv);
    dw_agg_k<<<dim3(2, 2, B_ * GRPS), 256>>>(wdw, wpw);
    kv_k<<<B_ * 64, 256>>>();

    cudaFuncSetAttribute(att_proj_mma_k,
                         cudaFuncAttributeMaxDynamicSharedMemorySize, K4_SM_TOT);
    att_proj_mma_k<<<dim3(32, 2, B_), 256, K4_SM_TOT>>>(
        wproj, x, gamma, beta, mean, var, out);
}

// round 8
// speedup vs baseline: 1.5377x; 1.5377x over previous
#include <cuda_runtime.h>
#include <cuda_bf16.h>
#include <stdint.h>

#define B_   8
#define C_   256
#define HW   4096
#define OC3  768
#define GRPS 96

// Scratch (alloc-free rule: __device__ globals)
__device__ float g_qkv[B_ * OC3 * HW];   // ~100.7 MB
__device__ float g_agg[B_ * OC3 * HW];   // ~100.7 MB
__device__ float g_kv [B_ * 64 * 72];    // per (b,head) 8x9 kv matrix

// ===========================================================================
// mma.sync / ldmatrix helpers (sm_80+ — legal on compute_103)
// ===========================================================================
__device__ __forceinline__ uint32_t smem_u32(const void* p) {
    uint32_t a;
    asm("{ .reg .u64 t; cvta.to.shared.u64 t, %1; cvt.u32.u64 %0, t; }"
        : "=r"(a) : "l"(p));
    return a;
}
__device__ __forceinline__ void ldsm_x4(uint32_t& r0, uint32_t& r1,
                                        uint32_t& r2, uint32_t& r3, uint32_t addr) {
    asm volatile("ldmatrix.sync.aligned.m8n8.x4.shared.b16 {%0,%1,%2,%3}, [%4];"
        : "=r"(r0), "=r"(r1), "=r"(r2), "=r"(r3) : "r"(addr));
}
__device__ __forceinline__ void ldsm_x2t(uint32_t& r0, uint32_t& r1, uint32_t addr) {
    asm volatile("ldmatrix.sync.aligned.m8n8.x2.trans.shared.b16 {%0,%1}, [%2];"
        : "=r"(r0), "=r"(r1) : "r"(addr));
}
__device__ __forceinline__ void mma_bf16(float& c0, float& c1, float& c2, float& c3,
    uint32_t a0, uint32_t a1, uint32_t a2, uint32_t a3, uint32_t b0, uint32_t b1) {
    asm volatile("mma.sync.aligned.m16n8k16.row.col.f32.bf16.bf16.f32 "
        "{%0,%1,%2,%3}, {%4,%5,%6,%7}, {%8,%9}, {%0,%1,%2,%3};"
        : "+f"(c0), "+f"(c1), "+f"(c2), "+f"(c3)
        : "r"(a0), "r"(a1), "r"(a2), "r"(a3), "r"(b0), "r"(b1));
}

// bf16 2-way split of a float4 (hi + lo packed as 4 bf16 each)
__device__ __forceinline__ void split4(float4 v, uint2& hi, uint2& lo) {
    __nv_bfloat162 h0 = __floats2bfloat162_rn(v.x, v.y);
    __nv_bfloat162 h1 = __floats2bfloat162_rn(v.z, v.w);
    float2 f0 = __bfloat1622float2(h0);
    float2 f1 = __bfloat1622float2(h1);
    __nv_bfloat162 l0 = __floats2bfloat162_rn(v.x - f0.x, v.y - f0.y);
    __nv_bfloat162 l1 = __floats2bfloat162_rn(v.z - f1.x, v.w - f1.y);
    hi = make_uint2(*(uint32_t*)&h0, *(uint32_t*)&h1);
    lo = make_uint2(*(uint32_t*)&l0, *(uint32_t*)&l1);
}

// ---------------------------------------------------------------------------
// K1 (HMMA): qkv[b,m,n] = sum_k w[m,k] * x[b,k,n]
// CTA 128x128, 512 threads, 4x4 warp grid (32x32 warp tiles), BK=32,
// 3-pass bf16 split, register prefetch of next chunk behind the MMAs.
// ---------------------------------------------------------------------------
#define K1_LDA 40
#define K1_LDB 136

__global__ __launch_bounds__(512) void qkv_mma_k(const float* __restrict__ x,
                                                 const float* __restrict__ w)
{
    __shared__ __nv_bfloat16 sA[2][128 * K1_LDA];   // hi, lo
    __shared__ __nv_bfloat16 sB[2][32 * K1_LDB];

    int tid = threadIdx.x, lane = tid & 31, wrp = tid >> 5;
    int b = blockIdx.z, n0 = blockIdx.x * 128, m0 = blockIdx.y * 128;
    const float* xb = x + (size_t)b * C_ * HW;
    float* ob = g_qkv + (size_t)b * OC3 * HW;

    int wm = (wrp >> 2) * 32, wn = (wrp & 3) * 32;
    float acc[2][4][4] = {};

    uint32_t aHi = smem_u32(&sA[0][0]), aLo = smem_u32(&sA[1][0]);
    uint32_t bHi = smem_u32(&sB[0][0]), bLo = smem_u32(&sB[1][0]);

    // prefetch chunk 0 into registers
    float4 pa[2], pb[2];
    #pragma unroll
    for (int i = 0; i < 2; i++) {
        int f4 = i * 512 + tid;
        pa[i] = *(const float4*)(w + (size_t)(m0 + (f4 >> 3)) * C_ + (f4 & 7) * 4);
        pb[i] = *(const float4*)(xb + (size_t)(f4 >> 5) * HW + n0 + (f4 & 31) * 4);
    }

    for (int kc = 0; kc < 8; kc++) {
        __syncthreads();             // smem free (prev chunk's MMAs done)
        #pragma unroll
        for (int i = 0; i < 2; i++) {
            int f4 = i * 512 + tid;
            uint2 hp, lp;
            split4(pa[i], hp, lp);
            *(uint2*)&sA[0][(f4 >> 3) * K1_LDA + (f4 & 7) * 4] = hp;
            *(uint2*)&sA[1][(f4 >> 3) * K1_LDA + (f4 & 7) * 4] = lp;
            split4(pb[i], hp, lp);
            *(uint2*)&sB[0][(f4 >> 5) * K1_LDB + (f4 & 31) * 4] = hp;
            *(uint2*)&sB[1][(f4 >> 5) * K1_LDB + (f4 & 31) * 4] = lp;
        }
        __syncthreads();
        if (kc < 7) {                // issue next chunk's loads behind the MMAs
            #pragma unroll
            for (int i = 0; i < 2; i++) {
                int f4 = i * 512 + tid;
                pa[i] = *(const float4*)(w + (size_t)(m0 + (f4 >> 3)) * C_
                                         + (kc + 1) * 32 + (f4 & 7) * 4);
                pb[i] = *(const float4*)(xb + (size_t)((kc + 1) * 32 + (f4 >> 5)) * HW
                                         + n0 + (f4 & 31) * 4);
            }
        }
        #pragma unroll
        for (int pass = 0; pass < 3; pass++) {
            uint32_t aB = (pass == 2) ? aLo : aHi;
            uint32_t bB = (pass == 1) ? bLo : bHi;
            #pragma unroll
            for (int ks = 0; ks < 2; ks++) {
                uint32_t af[2][4], bf[4][2];
                #pragma unroll
                for (int mi = 0; mi < 2; mi++)
                    ldsm_x4(af[mi][0], af[mi][1], af[mi][2], af[mi][3],
                        aB + (uint32_t)(((wm + mi * 16 + (lane & 15)) * K1_LDA
                                         + ks * 16 + (lane >> 4) * 8) * 2));
                #pragma unroll
                for (int ni = 0; ni < 4; ni++)
                    ldsm_x2t(bf[ni][0], bf[ni][1],
                        bB + (uint32_t)(((ks * 16 + (lane & 15)) * K1_LDB
                                         + wn + ni * 8) * 2));
                #pragma unroll
                for (int mi = 0; mi < 2; mi++)
                    #pragma unroll
                    for (int ni = 0; ni < 4; ni++)
                        mma_bf16(acc[mi][ni][0], acc[mi][ni][1],
                                 acc[mi][ni][2], acc[mi][ni][3],
                                 af[mi][0], af[mi][1], af[mi][2], af[mi][3],
                                 bf[ni][0], bf[ni][1]);
            }
        }
    }
    #pragma unroll
    for (int mi = 0; mi < 2; mi++) {
        int mr = m0 + wm + mi * 16 + (lane >> 2);
        #pragma unroll
        for (int ni = 0; ni < 4; ni++) {
            int n = n0 + wn + ni * 8 + (lane & 3) * 2;
            *(float2*)(ob + (size_t)mr * HW + n) =
                make_float2(acc[mi][ni][0], acc[mi][ni][1]);
            *(float2*)(ob + (size_t)(mr + 8) * HW + n) =
                make_float2(acc[mi][ni][2], acc[mi][ni][3]);
        }
    }
}

// ---------------------------------------------------------------------------
// K2: fused depthwise 5x5 (pad 2) + grouped 8x8 pointwise. (unchanged)
// ---------------------------------------------------------------------------
__global__ __launch_bounds__(256) void dw_agg_k(const float* __restrict__ wdw,
                                                const float* __restrict__ wpw)
{
    int bg = blockIdx.z;
    int b = bg / GRPS, g = bg % GRPS;
    int y0 = blockIdx.y * 32, x0 = blockIdx.x * 32;

    __shared__ float s[8][36][36];
    __shared__ float swd[8][25];
    __shared__ float swp[64];
    int tid = threadIdx.x;

    if (tid < 200) swd[tid / 25][tid % 25] = wdw[(size_t)(g * 8 + tid / 25) * 25 + tid % 25];
    if (tid < 64)  swp[tid] = wpw[(size_t)g * 64 + tid];

    const float* src = g_qkv + ((size_t)b * OC3 + g * 8) * HW;
    for (int i = tid; i < 8 * 36 * 36; i += 256) {
        int ch = i / 1296, r = (i % 1296) / 36, c = i % 36;
        int y = y0 + r - 2, x = x0 + c - 2;
        float v = 0.f;
        if ((unsigned)y < 64u && (unsigned)x < 64u) v = src[(size_t)ch * HW + y * 64 + x];
        s[ch][r][c] = v;
    }
    __syncthreads();

    float* dst = g_agg + ((size_t)b * OC3 + g * 8) * HW;
    for (int p = tid; p < 1024; p += 256) {
        int py = p >> 5, px = p & 31;
        float dwv[8];
        #pragma unroll
        for (int ch = 0; ch < 8; ch++) {
            float a = 0.f;
            #pragma unroll
            for (int dy = 0; dy < 5; dy++)
                #pragma unroll
                for (int dx = 0; dx < 5; dx++)
                    a = fmaf(s[ch][py + dy][px + dx], swd[ch][dy * 5 + dx], a);
            dwv[ch] = a;
        }
        int off = (y0 + py) * 64 + x0 + px;
        #pragma unroll
        for (int o = 0; o < 8; o++) {
            float a = 0.f;
            #pragma unroll
            for (int i2 = 0; i2 < 8; i2++) a = fmaf(swp[o * 8 + i2], dwv[i2], a);
            dst[(size_t)o * HW + off] = a;
        }
    }
}

// ---------------------------------------------------------------------------
// K3: kv reduction (unchanged)
// ---------------------------------------------------------------------------
__global__ __launch_bounds__(256) void kv_k()
{
    int bh = blockIdx.x;
    int b = bh >> 6, h = bh & 63;
    const float* base = (h < 32 ? g_qkv : g_agg) + ((size_t)b * OC3 + (h & 31) * 24) * HW;
    const float* kp = base + 8 * HW;
    const float* vp = base + 16 * HW;

    float acc[8][9] = {};
    for (int n = threadIdx.x; n < HW; n += 256) {
        float kr[8], vr[8];
        #pragma unroll
        for (int d = 0; d < 8; d++) {
            kr[d] = fmaxf(kp[(size_t)d * HW + n], 0.f);
            vr[d] = vp[(size_t)d * HW + n];
        }
        #pragma unroll
        for (int d = 0; d < 8; d++) {
            #pragma unroll
            for (int e = 0; e < 8; e++) acc[d][e] = fmaf(kr[d], vr[e], acc[d][e]);
            acc[d][8] += kr[d];
        }
    }
    __shared__ float sred[8][72];
    int w = threadIdx.x >> 5, lane = threadIdx.x & 31;
    #pragma unroll
    for (int d = 0; d < 8; d++)
        #pragma unroll
        for (int e = 0; e < 9; e++) {
            float v = acc[d][e];
            #pragma unroll
            for (int o = 16; o > 0; o >>= 1) v += __shfl_down_sync(0xffffffffu, v, o);
            if (lane == 0) sred[w][d * 9 + e] = v;
        }
    __syncthreads();
    if (threadIdx.x < 72) {
        float v = 0.f;
        #pragma unroll
        for (int w2 = 0; w2 < 8; w2++) v += sred[w2][threadIdx.x];
        g_kv[(size_t)bh * 72 + threadIdx.x] = v;
    }
}

// ---------------------------------------------------------------------------
// K4 (HMMA): fused attention + proj GEMM + BN + residual.
// CTA 128x128, 512 threads, 4x4 warp grid (32x32 warp tiles), BK=64.
// att generated on-the-fly per 8-head chunk, split bf16 hi/lo; 3-pass HMMA.
// ---------------------------------------------------------------------------
#define K4_LDA 72
#define K4_LDB 136
#define K4_SM_KV   0
#define K4_SM_A    18432                 // 4608 floats
#define K4_SM_B    (18432 + 36864)       // + 2*128*72*2
#define K4_SM_TOT  (18432 + 36864 + 34816)   // 90112 B

__global__ __launch_bounds__(512) void att_proj_mma_k(const float* __restrict__ wproj,
    const float* __restrict__ x, const float* __restrict__ gamma,
    const float* __restrict__ beta, const float* __restrict__ mean,
    const float* __restrict__ var, float* __restrict__ out)
{
    extern __shared__ char smc[];
    float* kv_s = (float*)(smc + K4_SM_KV);                  // 64*72
    __nv_bfloat16* sA = (__nv_bfloat16*)(smc + K4_SM_A);     // [2][128*72]
    __nv_bfloat16* sB = (__nv_bfloat16*)(smc + K4_SM_B);     // [2][64*136]

    int tid = threadIdx.x, lane = tid & 31, wrp = tid >> 5;
    int b = blockIdx.z, n0 = blockIdx.x * 128, m0 = blockIdx.y * 128;
    int wm = (wrp >> 2) * 32, wn = (wrp & 3) * 32;
    int nl = tid & 127, hslot = tid >> 7;   // 0..3

    for (int i = tid; i < 4608; i += 512) kv_s[i] = g_kv[(size_t)b * 4608 + i];

    float acc[2][4][4] = {};
    uint32_t aHi = smem_u32(sA), aLo = aHi + 128 * K4_LDA * 2;
    uint32_t bHi = smem_u32(sB), bLo = bHi + 64 * K4_LDB * 2;
    __nv_bfloat16* sAlo = sA + 128 * K4_LDA;
    __nv_bfloat16* sBlo = sB + 64 * K4_LDB;

    __syncthreads();

    for (int hc = 0; hc < 8; hc++) {
        if (hc) __syncthreads();
        // ---- stage W chunk: [m][k], 128x64 fp32 (2048 float4 / 512 thr) ----
        #pragma unroll
        for (int i = 0; i < 4; i++) {
            int f4 = i * 512 + tid, m = f4 >> 4, k4 = f4 & 15;
            float4 v = *(const float4*)(wproj + (size_t)(m0 + m) * 512 + hc * 64 + k4 * 4);
            uint2 hp, lp; split4(v, hp, lp);
            *(uint2*)&sA  [m * K4_LDA + k4 * 4] = hp;
            *(uint2*)&sAlo[m * K4_LDA + k4 * 4] = lp;
        }
        // ---- generate att chunk: 8 heads x 128 tokens -> [k][n] hi/lo ----
        #pragma unroll
        for (int i = 0; i < 2; i++) {
            int hl = hslot + i * 4;
            int h = hc * 8 + hl;
            const float* src = (h < 32 ? g_qkv : g_agg)
                             + ((size_t)b * OC3 + (h & 31) * 24) * HW + n0 + nl;
            float q[8];
            #pragma unroll
            for (int d = 0; d < 8; d++) q[d] = fmaxf(src[(size_t)d * HW], 0.f);
            const float* kvh = kv_s + h * 72;
            float den = 0.f;
            #pragma unroll
            for (int d = 0; d < 8; d++) den = fmaf(q[d], kvh[d * 9 + 8], den);
            float inv = 1.f / (den + 1e-15f);
            #pragma unroll
            for (int e = 0; e < 8; e++) {
                float s = 0.f;
                #pragma unroll
                for (int d = 0; d < 8; d++) s = fmaf(q[d], kvh[d * 9 + e], s);
                s *= inv;
                __nv_bfloat16 hbv = __float2bfloat16(s);
                __nv_bfloat16 lbv = __float2bfloat16(s - __bfloat162float(hbv));
                int row = hl * 8 + e;
                sB  [row * K4_LDB + nl] = hbv;
                sBlo[row * K4_LDB + nl] = lbv;
            }
        }
        __syncthreads();

        #pragma unroll
        for (int pass = 0; pass < 3; pass++) {
            uint32_t aB = (pass == 2) ? aLo : aHi;
            uint32_t bB = (pass == 1) ? bLo : bHi;
            #pragma unroll
            for (int ks = 0; ks < 4; ks++) {
                uint32_t af[2][4], bf[4][2];
                #pragma unroll
                for (int mi = 0; mi < 2; mi++)
                    ldsm_x4(af[mi][0], af[mi][1], af[mi][2], af[mi][3],
                        aB + (uint32_t)(((wm + mi * 16 + (lane & 15)) * K4_LDA
                                         + ks * 16 + (lane >> 4) * 8) * 2));
                #pragma unroll
                for (int ni = 0; ni < 4; ni++)
                    ldsm_x2t(bf[ni][0], bf[ni][1],
                        bB + (uint32_t)(((ks * 16 + (lane & 15)) * K4_LDB
                                         + wn + ni * 8) * 2));
                #pragma unroll
                for (int mi = 0; mi < 2; mi++)
                    #pragma unroll
                    for (int ni = 0; ni < 4; ni++)
                        mma_bf16(acc[mi][ni][0], acc[mi][ni][1],
                                 acc[mi][ni][2], acc[mi][ni][3],
                                 af[mi][0], af[mi][1], af[mi][2], af[mi][3],
                                 bf[ni][0], bf[ni][1]);
            }
        }
    }

    // ---- epilogue: BN + residual ----
    #pragma unroll
    for (int mi = 0; mi < 2; mi++) {
        #pragma unroll
        for (int half = 0; half < 2; half++) {
            int o = m0 + wm + mi * 16 + (lane >> 2) + half * 8;
            float invg = gamma[o] / sqrtf(var[o] + 1e-6f);
            float bias = beta[o] - mean[o] * invg;
            #pragma unroll
            for (int ni = 0; ni < 4; ni++) {
                int n = n0 + wn + ni * 8 + (lane & 3) * 2;
                size_t off = ((size_t)b * C_ + o) * HW + n;
                float2 xv = *(const float2*)(x + off);
                float2 r;
                r.x = xv.x + acc[mi][ni][half * 2 + 0] * invg + bias;
                r.y = xv.y + acc[mi][ni][half * 2 + 1] * invg + bias;
                *(float2*)(out + off) = r;
            }
        }
    }
}

// ---------------------------------------------------------------------------
extern "C" void kernel_launch(void* const* d_in, const int* in_sizes, int n_in,
                              void* d_out, int out_size)
{
    const float* x     = (const float*)d_in[0];
    const float* wqkv  = (const float*)d_in[1];
    const float* wdw   = (const float*)d_in[2];
    const float* wpw   = (const float*)d_in[3];
    const float* wproj = (const float*)d_in[4];
    const float* gamma = (const float*)d_in[5];
    const float* beta  = (const float*)d_in[6];
    const float* mean  = (const float*)d_in[7];
    const float* var   = (const float*)d_in[8];
    float* out = (float*)d_out;

    qkv_mma_k<<<dim3(32, 6, 8), 512>>>(x, wqkv);
    dw_agg_k<<<dim3(2, 2, B_ * GRPS), 256>>>(wdw, wpw);
    kv_k<<<B_ * 64, 256>>>();

    cudaFuncSetAttribute(att_proj_mma_k,
                         cudaFuncAttributeMaxDynamicSharedMemorySize, K4_SM_TOT);
    att_proj_mma_k<<<dim3(32, 2, B_), 512, K4_SM_TOT>>>(
        wproj, x, gamma, beta, mean, var, out);
}

// round 11
// speedup vs baseline: 1.5643x; 1.0173x over previous
#include <cuda_runtime.h>
#include <cuda_bf16.h>
#include <stdint.h>

#define B_   8
#define C_   256
#define HW   4096
#define OC3  768
#define GRPS 96

// Scratch (alloc-free rule: __device__ globals)
__device__ float g_qkv[B_ * OC3 * HW];   // ~100.7 MB
__device__ float g_agg[B_ * OC3 * HW];   // ~100.7 MB
__device__ float g_kv [B_ * 64 * 72];    // per (b,head) 8x9 kv matrix

// Preconverted bf16 hi/lo operand buffers
__device__ __align__(16) __nv_bfloat16 g_xhi[B_ * C_ * HW];
__device__ __align__(16) __nv_bfloat16 g_xlo[B_ * C_ * HW];
__device__ __align__(16) __nv_bfloat16 g_wqhi[OC3 * C_];
__device__ __align__(16) __nv_bfloat16 g_wqlo[OC3 * C_];
__device__ __align__(16) __nv_bfloat16 g_wphi[C_ * 512];
__device__ __align__(16) __nv_bfloat16 g_wplo[C_ * 512];

// ===========================================================================
// helpers
// ===========================================================================
__device__ __forceinline__ uint32_t smem_u32(const void* p) {
    uint32_t a;
    asm("{ .reg .u64 t; cvta.to.shared.u64 t, %1; cvt.u32.u64 %0, t; }"
        : "=r"(a) : "l"(p));
    return a;
}
__device__ __forceinline__ void ldsm_x4(uint32_t& r0, uint32_t& r1,
                                        uint32_t& r2, uint32_t& r3, uint32_t addr) {
    asm volatile("ldmatrix.sync.aligned.m8n8.x4.shared.b16 {%0,%1,%2,%3}, [%4];"
        : "=r"(r0), "=r"(r1), "=r"(r2), "=r"(r3) : "r"(addr));
}
__device__ __forceinline__ void ldsm_x2t(uint32_t& r0, uint32_t& r1, uint32_t addr) {
    asm volatile("ldmatrix.sync.aligned.m8n8.x2.trans.shared.b16 {%0,%1}, [%2];"
        : "=r"(r0), "=r"(r1) : "r"(addr));
}
__device__ __forceinline__ void mma_bf16(float& c0, float& c1, float& c2, float& c3,
    uint32_t a0, uint32_t a1, uint32_t a2, uint32_t a3, uint32_t b0, uint32_t b1) {
    asm volatile("mma.sync.aligned.m16n8k16.row.col.f32.bf16.bf16.f32 "
        "{%0,%1,%2,%3}, {%4,%5,%6,%7}, {%8,%9}, {%0,%1,%2,%3};"
        : "+f"(c0), "+f"(c1), "+f"(c2), "+f"(c3)
        : "r"(a0), "r"(a1), "r"(a2), "r"(a3), "r"(b0), "r"(b1));
}
__device__ __forceinline__ void cpa16(uint32_t dst, const void* src) {
    asm volatile("cp.async.ca.shared.global [%0], [%1], 16;" :: "r"(dst), "l"(src));
}
#define CP_COMMIT() asm volatile("cp.async.commit_group;" ::: "memory")
#define CP_WAIT0()  asm volatile("cp.async.wait_group 0;" ::: "memory")

__device__ __forceinline__ void split4(float4 v, uint2& hi, uint2& lo) {
    __nv_bfloat162 h0 = __floats2bfloat162_rn(v.x, v.y);
    __nv_bfloat162 h1 = __floats2bfloat162_rn(v.z, v.w);
    float2 f0 = __bfloat1622float2(h0);
    float2 f1 = __bfloat1622float2(h1);
    __nv_bfloat162 l0 = __floats2bfloat162_rn(v.x - f0.x, v.y - f0.y);
    __nv_bfloat162 l1 = __floats2bfloat162_rn(v.z - f1.x, v.w - f1.y);
    hi = make_uint2(*(uint32_t*)&h0, *(uint32_t*)&h1);
    lo = make_uint2(*(uint32_t*)&l0, *(uint32_t*)&l1);
}

// ---------------------------------------------------------------------------
// K0a/K0b: preconvert fp32 -> bf16 hi/lo
// ---------------------------------------------------------------------------
__global__ __launch_bounds__(256) void conv_x_k(const float* __restrict__ x)
{
    size_t i4 = (size_t)blockIdx.x * 256 + threadIdx.x;   // float4 index
    float4 v = *(const float4*)(x + i4 * 4);
    uint2 hp, lp; split4(v, hp, lp);
    *(uint2*)(g_xhi + i4 * 4) = hp;
    *(uint2*)(g_xlo + i4 * 4) = lp;
}
__global__ __launch_bounds__(256) void conv_w_k(const float* __restrict__ wq,
                                                const float* __restrict__ wp)
{
    int i4 = blockIdx.x * 256 + threadIdx.x;
    if (i4 < 49152) {                         // wqkv: 768*256/4
        float4 v = *(const float4*)(wq + (size_t)i4 * 4);
        uint2 hp, lp; split4(v, hp, lp);
        *(uint2*)(g_wqhi + (size_t)i4 * 4) = hp;
        *(uint2*)(g_wqlo + (size_t)i4 * 4) = lp;
    } else {                                  // wproj: 256*512/4
        int j = i4 - 49152;
        float4 v = *(const float4*)(wp + (size_t)j * 4);
        uint2 hp, lp; split4(v, hp, lp);
        *(uint2*)(g_wphi + (size_t)j * 4) = hp;
        *(uint2*)(g_wplo + (size_t)j * 4) = lp;
    }
}

// ---------------------------------------------------------------------------
// K1 (HMMA + cp.async double buffer): qkv[b,m,n] = sum_k w[m,k]*x[b,k,n]
// CTA 128x128, 512 thr, 4x4 warps (32x32 tiles), BK=64, 3-pass bf16 split.
// Stage (per buf): AHI 128x144B | ALO | BHI 64x272B | BLO   = 71680 B
// ---------------------------------------------------------------------------
#define K1_ST   71680
#define K1_ALO  18432
#define K1_BOFF 36864
#define K1_BLO  17408
#define K1_SMEM (2 * K1_ST)

__global__ __launch_bounds__(512) void qkv_mma_k()
{
    extern __shared__ char smc[];
    uint32_t sb = smem_u32(smc);
    int tid = threadIdx.x, lane = tid & 31, wrp = tid >> 5;
    int b = blockIdx.z, n0 = blockIdx.x * 128, m0 = blockIdx.y * 128;
    int wm = (wrp >> 2) * 32, wn = (wrp & 3) * 32;
    float acc[2][4][4] = {};
    float* ob = g_qkv + (size_t)b * OC3 * HW;

    // stage(kc, buf): A rows 128 x 8 segs, B rows 64 x 16 segs (hi+lo each)
    auto stage = [&](int kc, int buf) {
        uint32_t d = sb + buf * K1_ST;
        #pragma unroll
        for (int i = 0; i < 2; i++) {
            int c = i * 512 + tid;                  // 0..1023
            int row = c >> 3, seg = c & 7;
            size_t so = (size_t)(m0 + row) * C_ + kc * 64 + seg * 8;
            uint32_t dd = d + row * 144 + seg * 16;
            cpa16(dd, g_wqhi + so);
            cpa16(dd + K1_ALO, g_wqlo + so);
        }
        #pragma unroll
        for (int i = 0; i < 2; i++) {
            int c = i * 512 + tid;
            int row = c >> 4, seg = c & 15;
            size_t so = ((size_t)b * C_ + kc * 64 + row) * HW + n0 + seg * 8;
            uint32_t dd = d + K1_BOFF + row * 272 + seg * 16;
            cpa16(dd, g_xhi + so);
            cpa16(dd + K1_BLO, g_xlo + so);
        }
    };

    stage(0, 0); CP_COMMIT();
    int buf = 0;
    for (int kc = 0; kc < 4; kc++) {
        CP_WAIT0();
        __syncthreads();
        if (kc < 3) { stage(kc + 1, buf ^ 1); CP_COMMIT(); }
        uint32_t aBase = sb + buf * K1_ST;
        uint32_t bBase = aBase + K1_BOFF;
        #pragma unroll
        for (int pass = 0; pass < 3; pass++) {
            uint32_t aB = aBase + ((pass == 2) ? K1_ALO : 0);
            uint32_t bB = bBase + ((pass == 1) ? K1_BLO : 0);
            #pragma unroll
            for (int ks = 0; ks < 4; ks++) {
                uint32_t af[2][4], bf[4][2];
                #pragma unroll
                for (int mi = 0; mi < 2; mi++)
                    ldsm_x4(af[mi][0], af[mi][1], af[mi][2], af[mi][3],
                        aB + (uint32_t)((wm + mi * 16 + (lane & 15)) * 144
                                        + (ks * 16 + (lane >> 4) * 8) * 2));
                #pragma unroll
                for (int ni = 0; ni < 4; ni++)
                    ldsm_x2t(bf[ni][0], bf[ni][1],
                        bB + (uint32_t)((ks * 16 + (lane & 15)) * 272
                                        + (wn + ni * 8) * 2));
                #pragma unroll
                for (int mi = 0; mi < 2; mi++)
                    #pragma unroll
                    for (int ni = 0; ni < 4; ni++)
                        mma_bf16(acc[mi][ni][0], acc[mi][ni][1],
                                 acc[mi][ni][2], acc[mi][ni][3],
                                 af[mi][0], af[mi][1], af[mi][2], af[mi][3],
                                 bf[ni][0], bf[ni][1]);
            }
        }
        buf ^= 1;
    }
    #pragma unroll
    for (int mi = 0; mi < 2; mi++) {
        int mr = m0 + wm + mi * 16 + (lane >> 2);
        #pragma unroll
        for (int ni = 0; ni < 4; ni++) {
            int n = n0 + wn + ni * 8 + (lane & 3) * 2;
            *(float2*)(ob + (size_t)mr * HW + n) =
                make_float2(acc[mi][ni][0], acc[mi][ni][1]);
            *(float2*)(ob + (size_t)(mr + 8) * HW + n) =
                make_float2(acc[mi][ni][2], acc[mi][ni][3]);
        }
    }
}

// ---------------------------------------------------------------------------
// K2: fused depthwise 5x5 (pad 2) + grouped 8x8 pointwise. (unchanged)
// ---------------------------------------------------------------------------
__global__ __launch_bounds__(256) void dw_agg_k(const float* __restrict__ wdw,
                                                const float* __restrict__ wpw)
{
    int bg = blockIdx.z;
    int b = bg / GRPS, g = bg % GRPS;
    int y0 = blockIdx.y * 32, x0 = blockIdx.x * 32;

    __shared__ float s[8][36][36];
    __shared__ float swd[8][25];
    __shared__ float swp[64];
    int tid = threadIdx.x;

    if (tid < 200) swd[tid / 25][tid % 25] = wdw[(size_t)(g * 8 + tid / 25) * 25 + tid % 25];
    if (tid < 64)  swp[tid] = wpw[(size_t)g * 64 + tid];

    const float* src = g_qkv + ((size_t)b * OC3 + g * 8) * HW;
    for (int i = tid; i < 8 * 36 * 36; i += 256) {
        int ch = i / 1296, r = (i % 1296) / 36, c = i % 36;
        int y = y0 + r - 2, x = x0 + c - 2;
        float v = 0.f;
        if ((unsigned)y < 64u && (unsigned)x < 64u) v = src[(size_t)ch * HW + y * 64 + x];
        s[ch][r][c] = v;
    }
    __syncthreads();

    float* dst = g_agg + ((size_t)b * OC3 + g * 8) * HW;
    for (int p = tid; p < 1024; p += 256) {
        int py = p >> 5, px = p & 31;
        float dwv[8];
        #pragma unroll
        for (int ch = 0; ch < 8; ch++) {
            float a = 0.f;
            #pragma unroll
            for (int dy = 0; dy < 5; dy++)
                #pragma unroll
                for (int dx = 0; dx < 5; dx++)
                    a = fmaf(s[ch][py + dy][px + dx], swd[ch][dy * 5 + dx], a);
            dwv[ch] = a;
        }
        int off = (y0 + py) * 64 + x0 + px;
        #pragma unroll
        for (int o = 0; o < 8; o++) {
            float a = 0.f;
            #pragma unroll
            for (int i2 = 0; i2 < 8; i2++) a = fmaf(swp[o * 8 + i2], dwv[i2], a);
            dst[(size_t)o * HW + off] = a;
        }
    }
}

// ---------------------------------------------------------------------------
// K3: kv reduction (unchanged)
// ---------------------------------------------------------------------------
__global__ __launch_bounds__(256) void kv_k()
{
    int bh = blockIdx.x;
    int b = bh >> 6, h = bh & 63;
    const float* base = (h < 32 ? g_qkv : g_agg) + ((size_t)b * OC3 + (h & 31) * 24) * HW;
    const float* kp = base + 8 * HW;
    const float* vp = base + 16 * HW;

    float acc[8][9] = {};
    for (int n = threadIdx.x; n < HW; n += 256) {
        float kr[8], vr[8];
        #pragma unroll
        for (int d = 0; d < 8; d++) {
            kr[d] = fmaxf(kp[(size_t)d * HW + n], 0.f);
            vr[d] = vp[(size_t)d * HW + n];
        }
        #pragma unroll
        for (int d = 0; d < 8; d++) {
            #pragma unroll
            for (int e = 0; e < 8; e++) acc[d][e] = fmaf(kr[d], vr[e], acc[d][e]);
            acc[d][8] += kr[d];
        }
    }
    __shared__ float sred[8][72];
    int w = threadIdx.x >> 5, lane = threadIdx.x & 31;
    #pragma unroll
    for (int d = 0; d < 8; d++)
        #pragma unroll
        for (int e = 0; e < 9; e++) {
            float v = acc[d][e];
            #pragma unroll
            for (int o = 16; o > 0; o >>= 1) v += __shfl_down_sync(0xffffffffu, v, o);
            if (lane == 0) sred[w][d * 9 + e] = v;
        }
    __syncthreads();
    if (threadIdx.x < 72) {
        float v = 0.f;
        #pragma unroll
        for (int w2 = 0; w2 < 8; w2++) v += sred[w2][threadIdx.x];
        g_kv[(size_t)bh * 72 + threadIdx.x] = v;
    }
}

// ---------------------------------------------------------------------------
// K4 (HMMA): fused attention + proj GEMM + BN + residual.
// CTA 128x128, 512 thr, 4x4 warps, BK=64, 8 chunks.
// W staged via cp.async double buffer from preconverted g_wphi/lo;
// att generated into double-buffered smem; q prefetched into registers.
// SMEM: kv 18432 | W stages 2x36864 | att stages 2x34816 = 161792 B
// ---------------------------------------------------------------------------
#define K4_WOFF  18432
#define K4_WST   36864
#define K4_AOFF  (18432 + 2 * K4_WST)          // 92160
#define K4_AST   34816
#define K4_ALO2  17408
#define K4_SMEM  (K4_AOFF + 2 * K4_AST)        // 161792

__global__ __launch_bounds__(512) void att_proj_mma_k(
    const float* __restrict__ x, const float* __restrict__ gamma,
    const float* __restrict__ beta, const float* __restrict__ mean,
    const float* __restrict__ var, float* __restrict__ out)
{
    extern __shared__ char smc[];
    float* kv_s = (float*)smc;
    uint32_t sb = smem_u32(smc);

    int tid = threadIdx.x, lane = tid & 31, wrp = tid >> 5;
    int b = blockIdx.z, n0 = blockIdx.x * 128, m0 = blockIdx.y * 128;
    int wm = (wrp >> 2) * 32, wn = (wrp & 3) * 32;
    int nl = tid & 127, hslot = tid >> 7;     // 0..3

    for (int i = tid; i < 4608; i += 512) kv_s[i] = g_kv[(size_t)b * 4608 + i];

    float acc[2][4][4] = {};

    auto stageW = [&](int hc, int s) {
        uint32_t d = sb + K4_WOFF + s * K4_WST;
        #pragma unroll
        for (int i = 0; i < 2; i++) {
            int c = i * 512 + tid;              // 0..1023
            int row = c >> 3, seg = c & 7;
            size_t so = (size_t)(m0 + row) * 512 + hc * 64 + seg * 8;
            uint32_t dd = d + row * 144 + seg * 16;
            cpa16(dd, g_wphi + so);
            cpa16(dd + 18432, g_wplo + so);
        }
    };

    float qr[2][8];
    auto preloadQ = [&](int hc) {
        #pragma unroll
        for (int i = 0; i < 2; i++) {
            int h = hc * 8 + hslot + i * 4;
            const float* src = (h < 32 ? g_qkv : g_agg)
                             + ((size_t)b * OC3 + (h & 31) * 24) * HW + n0 + nl;
            #pragma unroll
            for (int d = 0; d < 8; d++) qr[i][d] = fmaxf(src[(size_t)d * HW], 0.f);
        }
    };

    stageW(0, 0); CP_COMMIT();
    preloadQ(0);
    __syncthreads();          // kv_s ready

    for (int hc = 0; hc < 8; hc++) {
        CP_WAIT0();
        __syncthreads();      // W(hc) visible; all MMA(hc-1) done
        if (hc < 7) { stageW(hc + 1, (hc + 1) & 1); CP_COMMIT(); }

        // ---- generate att chunk from prefetched q -> attbuf[hc&1] ----
        __nv_bfloat16* aHiP = (__nv_bfloat16*)(smc + K4_AOFF + (hc & 1) * K4_AST);
        __nv_bfloat16* aLoP = aHiP + 8704;      // +17408 B
        #pragma unroll
        for (int i = 0; i < 2; i++) {
            int hl = hslot + i * 4;
            int h = hc * 8 + hl;
            const float* kvh = kv_s + h * 72;
            float den = 0.f;
            #pragma unroll
            for (int d = 0; d < 8; d++) den = fmaf(qr[i][d], kvh[d * 9 + 8], den);
            float inv = 1.f / (den + 1e-15f);
            #pragma unroll
            for (int e = 0; e < 8; e++) {
                float s = 0.f;
                #pragma unroll
                for (int d = 0; d < 8; d++) s = fmaf(qr[i][d], kvh[d * 9 + e], s);
                s *= inv;
                __nv_bfloat16 hbv = __float2bfloat16(s);
                __nv_bfloat16 lbv = __float2bfloat16(s - __bfloat162float(hbv));
                int row = hl * 8 + e;
                aHiP[row * 136 + nl] = hbv;
                aLoP[row * 136 + nl] = lbv;
            }
        }
        if (hc < 7) preloadQ(hc + 1);           // global loads behind MMA
        __syncthreads();                        // att ready

        uint32_t wBase = sb + K4_WOFF + (hc & 1) * K4_WST;
        uint32_t bBase = sb + K4_AOFF + (hc & 1) * K4_AST;
        #pragma unroll
        for (int pass = 0; pass < 3; pass++) {
            uint32_t aB = wBase + ((pass == 2) ? 18432 : 0);
            uint32_t bB = bBase + ((pass == 1) ? K4_ALO2 : 0);
            #pragma unroll
            for (int ks = 0; ks < 4; ks++) {
                uint32_t af[2][4], bf[4][2];
                #pragma unroll
                for (int mi = 0; mi < 2; mi++)
                    ldsm_x4(af[mi][0], af[mi][1], af[mi][2], af[mi][3],
                        aB + (uint32_t)((wm + mi * 16 + (lane & 15)) * 144
                                        + (ks * 16 + (lane >> 4) * 8) * 2));
                #pragma unroll
                for (int ni = 0; ni < 4; ni++)
                    ldsm_x2t(bf[ni][0], bf[ni][1],
                        bB + (uint32_t)((ks * 16 + (lane & 15)) * 272
                                        + (wn + ni * 8) * 2));
                #pragma unroll
                for (int mi = 0; mi < 2; mi++)
                    #pragma unroll
                    for (int ni = 0; ni < 4; ni++)
                        mma_bf16(acc[mi][ni][0], acc[mi][ni][1],
                                 acc[mi][ni][2], acc[mi][ni][3],
                                 af[mi][0], af[mi][1], af[mi][2], af[mi][3],
                                 bf[ni][0], bf[ni][1]);
            }
        }
    }

    // ---- epilogue: BN + residual ----
    #pragma unroll
    for (int mi = 0; mi < 2; mi++) {
        #pragma unroll
        for (int half = 0; half < 2; half++) {
            int o = m0 + wm + mi * 16 + (lane >> 2) + half * 8;
            float invg = gamma[o] / sqrtf(var[o] + 1e-6f);
            float bias = beta[o] - mean[o] * invg;
            #pragma unroll
            for (int ni = 0; ni < 4; ni++) {
                int n = n0 + wn + ni * 8 + (lane & 3) * 2;
                size_t off = ((size_t)b * C_ + o) * HW + n;
                float2 xv = *(const float2*)(x + off);
                float2 r;
                r.x = xv.x + acc[mi][ni][half * 2 + 0] * invg + bias;
                r.y = xv.y + acc[mi][ni][half * 2 + 1] * invg + bias;
                *(float2*)(out + off) = r;
            }
        }
    }
}

// ---------------------------------------------------------------------------
extern "C" void kernel_launch(void* const* d_in, const int* in_sizes, int n_in,
                              void* d_out, int out_size)
{
    const float* x     = (const float*)d_in[0];
    const float* wqkv  = (const float*)d_in[1];
    const float* wdw   = (const float*)d_in[2];
    const float* wpw   = (const float*)d_in[3];
    const float* wproj = (const float*)d_in[4];
    const float* gamma = (const float*)d_in[5];
    const float* beta  = (const float*)d_in[6];
    const float* mean  = (const float*)d_in[7];
    const float* var   = (const float*)d_in[8];
    float* out = (float*)d_out;

    conv_x_k<<<8192, 256>>>(x);
    conv_w_k<<<320, 256>>>(wqkv, wproj);

    cudaFuncSetAttribute(qkv_mma_k, cudaFuncAttributeMaxDynamicSharedMemorySize, K1_SMEM);
    qkv_mma_k<<<dim3(32, 6, 8), 512, K1_SMEM>>>();

    dw_agg_k<<<dim3(2, 2, B_ * GRPS), 256>>>(wdw, wpw);
    kv_k<<<B_ * 64, 256>>>();

    cudaFuncSetAttribute(att_proj_mma_k, cudaFuncAttributeMaxDynamicSharedMemorySize, K4_SMEM);
    att_proj_mma_k<<<dim3(32, 2, B_), 512, K4_SMEM>>>(x, gamma, beta, mean, var, out);
}

// round 14
// speedup vs baseline: 2.2909x; 1.4646x over previous
#include <cuda_runtime.h>
#include <cuda_bf16.h>
#include <stdint.h>

#define B_   8
#define C_   256
#define HW   4096
#define OC3  768
#define GRPS 96

// Scratch (alloc-free rule: __device__ globals)
__device__ float g_qkv[B_ * OC3 * HW];   // ~100.7 MB
__device__ float g_agg[B_ * OC3 * HW];   // ~100.7 MB
__device__ float g_kv [B_ * 64 * 72];    // per (b,head) 8x9 kv matrix

// Preconverted bf16 hi/lo operand buffers
__device__ __align__(16) __nv_bfloat16 g_xhi[B_ * C_ * HW];
__device__ __align__(16) __nv_bfloat16 g_xlo[B_ * C_ * HW];
__device__ __align__(16) __nv_bfloat16 g_wqhi[OC3 * C_];
__device__ __align__(16) __nv_bfloat16 g_wqlo[OC3 * C_];
__device__ __align__(16) __nv_bfloat16 g_wphi[C_ * 512];
__device__ __align__(16) __nv_bfloat16 g_wplo[C_ * 512];

// ===========================================================================
// helpers
// ===========================================================================
__device__ __forceinline__ uint32_t smem_u32(const void* p) {
    uint32_t a;
    asm("{ .reg .u64 t; cvta.to.shared.u64 t, %1; cvt.u32.u64 %0, t; }"
        : "=r"(a) : "l"(p));
    return a;
}
__device__ __forceinline__ void ldsm_x4(uint32_t& r0, uint32_t& r1,
                                        uint32_t& r2, uint32_t& r3, uint32_t addr) {
    asm volatile("ldmatrix.sync.aligned.m8n8.x4.shared.b16 {%0,%1,%2,%3}, [%4];"
        : "=r"(r0), "=r"(r1), "=r"(r2), "=r"(r3) : "r"(addr));
}
__device__ __forceinline__ void ldsm_x2t(uint32_t& r0, uint32_t& r1, uint32_t addr) {
    asm volatile("ldmatrix.sync.aligned.m8n8.x2.trans.shared.b16 {%0,%1}, [%2];"
        : "=r"(r0), "=r"(r1) : "r"(addr));
}
__device__ __forceinline__ void mma_bf16(float& c0, float& c1, float& c2, float& c3,
    uint32_t a0, uint32_t a1, uint32_t a2, uint32_t a3, uint32_t b0, uint32_t b1) {
    asm volatile("mma.sync.aligned.m16n8k16.row.col.f32.bf16.bf16.f32 "
        "{%0,%1,%2,%3}, {%4,%5,%6,%7}, {%8,%9}, {%0,%1,%2,%3};"
        : "+f"(c0), "+f"(c1), "+f"(c2), "+f"(c3)
        : "r"(a0), "r"(a1), "r"(a2), "r"(a3), "r"(b0), "r"(b1));
}
__device__ __forceinline__ void cpa16(uint32_t dst, const void* src) {
    asm volatile("cp.async.ca.shared.global [%0], [%1], 16;" :: "r"(dst), "l"(src));
}
#define CP_COMMIT() asm volatile("cp.async.commit_group;" ::: "memory")
#define CP_WAIT0()  asm volatile("cp.async.wait_group 0;" ::: "memory")

__device__ __forceinline__ void split4(float4 v, uint2& hi, uint2& lo) {
    __nv_bfloat162 h0 = __floats2bfloat162_rn(v.x, v.y);
    __nv_bfloat162 h1 = __floats2bfloat162_rn(v.z, v.w);
    float2 f0 = __bfloat1622float2(h0);
    float2 f1 = __bfloat1622float2(h1);
    __nv_bfloat162 l0 = __floats2bfloat162_rn(v.x - f0.x, v.y - f0.y);
    __nv_bfloat162 l1 = __floats2bfloat162_rn(v.z - f1.x, v.w - f1.y);
    hi = make_uint2(*(uint32_t*)&h0, *(uint32_t*)&h1);
    lo = make_uint2(*(uint32_t*)&l0, *(uint32_t*)&l1);
}

// ---------------------------------------------------------------------------
// K0a/K0b: preconvert fp32 -> bf16 hi/lo
// ---------------------------------------------------------------------------
__global__ __launch_bounds__(256) void conv_x_k(const float* __restrict__ x)
{
    size_t i4 = (size_t)blockIdx.x * 256 + threadIdx.x;   // float4 index
    float4 v = *(const float4*)(x + i4 * 4);
    uint2 hp, lp; split4(v, hp, lp);
    *(uint2*)(g_xhi + i4 * 4) = hp;
    *(uint2*)(g_xlo + i4 * 4) = lp;
}
__global__ __launch_bounds__(256) void conv_w_k(const float* __restrict__ wq,
                                                const float* __restrict__ wp)
{
    int i4 = blockIdx.x * 256 + threadIdx.x;
    if (i4 < 49152) {                         // wqkv: 768*256/4
        float4 v = *(const float4*)(wq + (size_t)i4 * 4);
        uint2 hp, lp; split4(v, hp, lp);
        *(uint2*)(g_wqhi + (size_t)i4 * 4) = hp;
        *(uint2*)(g_wqlo + (size_t)i4 * 4) = lp;
    } else {                                  // wproj: 256*512/4
        int j = i4 - 49152;
        float4 v = *(const float4*)(wp + (size_t)j * 4);
        uint2 hp, lp; split4(v, hp, lp);
        *(uint2*)(g_wphi + (size_t)j * 4) = hp;
        *(uint2*)(g_wplo + (size_t)j * 4) = lp;
    }
}

// ---------------------------------------------------------------------------
// K1 (HMMA + cp.async double buffer): qkv[b,m,n] = sum_k w[m,k]*x[b,k,n]
// CTA 128x128, 512 thr, 4x4 warps (32x32 tiles), BK=64, 3-pass bf16 split.
// ---------------------------------------------------------------------------
#define K1_ST   71680
#define K1_ALO  18432
#define K1_BOFF 36864
#define K1_BLO  17408
#define K1_SMEM (2 * K1_ST)

__global__ __launch_bounds__(512) void qkv_mma_k()
{
    extern __shared__ char smc[];
    uint32_t sb = smem_u32(smc);
    int tid = threadIdx.x, lane = tid & 31, wrp = tid >> 5;
    int b = blockIdx.z, n0 = blockIdx.x * 128, m0 = blockIdx.y * 128;
    int wm = (wrp >> 2) * 32, wn = (wrp & 3) * 32;
    float acc[2][4][4] = {};
    float* ob = g_qkv + (size_t)b * OC3 * HW;

    auto stage = [&](int kc, int buf) {
        uint32_t d = sb + buf * K1_ST;
        #pragma unroll
        for (int i = 0; i < 2; i++) {
            int c = i * 512 + tid;
            int row = c >> 3, seg = c & 7;
            size_t so = (size_t)(m0 + row) * C_ + kc * 64 + seg * 8;
            uint32_t dd = d + row * 144 + seg * 16;
            cpa16(dd, g_wqhi + so);
            cpa16(dd + K1_ALO, g_wqlo + so);
        }
        #pragma unroll
        for (int i = 0; i < 2; i++) {
            int c = i * 512 + tid;
            int row = c >> 4, seg = c & 15;
            size_t so = ((size_t)b * C_ + kc * 64 + row) * HW + n0 + seg * 8;
            uint32_t dd = d + K1_BOFF + row * 272 + seg * 16;
            cpa16(dd, g_xhi + so);
            cpa16(dd + K1_BLO, g_xlo + so);
        }
    };

    stage(0, 0); CP_COMMIT();
    int buf = 0;
    for (int kc = 0; kc < 4; kc++) {
        CP_WAIT0();
        __syncthreads();
        if (kc < 3) { stage(kc + 1, buf ^ 1); CP_COMMIT(); }
        uint32_t aBase = sb + buf * K1_ST;
        uint32_t bBase = aBase + K1_BOFF;
        #pragma unroll
        for (int pass = 0; pass < 3; pass++) {
            uint32_t aB = aBase + ((pass == 2) ? K1_ALO : 0);
            uint32_t bB = bBase + ((pass == 1) ? K1_BLO : 0);
            #pragma unroll
            for (int ks = 0; ks < 4; ks++) {
                uint32_t af[2][4], bf[4][2];
                #pragma unroll
                for (int mi = 0; mi < 2; mi++)
                    ldsm_x4(af[mi][0], af[mi][1], af[mi][2], af[mi][3],
                        aB + (uint32_t)((wm + mi * 16 + (lane & 15)) * 144
                                        + (ks * 16 + (lane >> 4) * 8) * 2));
                #pragma unroll
                for (int ni = 0; ni < 4; ni++)
                    ldsm_x2t(bf[ni][0], bf[ni][1],
                        bB + (uint32_t)((ks * 16 + (lane & 15)) * 272
                                        + (wn + ni * 8) * 2));
                #pragma unroll
                for (int mi = 0; mi < 2; mi++)
                    #pragma unroll
                    for (int ni = 0; ni < 4; ni++)
                        mma_bf16(acc[mi][ni][0], acc[mi][ni][1],
                                 acc[mi][ni][2], acc[mi][ni][3],
                                 af[mi][0], af[mi][1], af[mi][2], af[mi][3],
                                 bf[ni][0], bf[ni][1]);
            }
        }
        buf ^= 1;
    }
    #pragma unroll
    for (int mi = 0; mi < 2; mi++) {
        int mr = m0 + wm + mi * 16 + (lane >> 2);
        #pragma unroll
        for (int ni = 0; ni < 4; ni++) {
            int n = n0 + wn + ni * 8 + (lane & 3) * 2;
            *(float2*)(ob + (size_t)mr * HW + n) =
                make_float2(acc[mi][ni][0], acc[mi][ni][1]);
            *(float2*)(ob + (size_t)(mr + 8) * HW + n) =
                make_float2(acc[mi][ni][2], acc[mi][ni][3]);
        }
    }
}

// ---------------------------------------------------------------------------
// K2 (REWRITTEN): fused depthwise 5x5 (pad 2) + grouped 8x8 pointwise.
// Thread = (px = tid&31, vertical strip py0 = (tid>>5)*4 .. +3).
// Per channel, per dx: one 8-value column feeds 5 dy taps x 4 pixels
// (LDS 800 -> 320/thread). acc[4][8] in registers; 3 CTAs/SM.
// ---------------------------------------------------------------------------
__global__ __launch_bounds__(256, 3) void dw_agg_k(const float* __restrict__ wdw,
                                                   const float* __restrict__ wpw)
{
    int bg = blockIdx.z;
    int b = bg / GRPS, g = bg % GRPS;
    int y0 = blockIdx.y * 32, x0 = blockIdx.x * 32;

    __shared__ float s[8][36][36];
    __shared__ float swd[8][25];
    __shared__ float swp[64];
    int tid = threadIdx.x;

    if (tid < 200) swd[tid / 25][tid % 25] = wdw[(size_t)(g * 8 + tid / 25) * 25 + tid % 25];
    if (tid < 64)  swp[tid] = wpw[(size_t)g * 64 + tid];

    const float* src = g_qkv + ((size_t)b * OC3 + g * 8) * HW;
    for (int i = tid; i < 8 * 36 * 36; i += 256) {
        int ch = i / 1296, r = (i % 1296) / 36, c = i % 36;
        int y = y0 + r - 2, x = x0 + c - 2;
        float v = 0.f;
        if ((unsigned)y < 64u && (unsigned)x < 64u) v = src[(size_t)ch * HW + y * 64 + x];
        s[ch][r][c] = v;
    }
    __syncthreads();

    int px = tid & 31;
    int py0 = (tid >> 5) * 4;

    float acc[4][8] = {};
    for (int ch = 0; ch < 8; ch++) {
        float dwv[4] = {0.f, 0.f, 0.f, 0.f};
        #pragma unroll
        for (int dx = 0; dx < 5; dx++) {
            float col[8];
            #pragma unroll
            for (int r = 0; r < 8; r++) col[r] = s[ch][py0 + r][px + dx];
            #pragma unroll
            for (int dy = 0; dy < 5; dy++) {
                float wv = swd[ch][dy * 5 + dx];
                #pragma unroll
                for (int p = 0; p < 4; p++) dwv[p] = fmaf(col[p + dy], wv, dwv[p]);
            }
        }
        #pragma unroll
        for (int o = 0; o < 8; o++) {
            float wpv = swp[o * 8 + ch];
            #pragma unroll
            for (int p = 0; p < 4; p++) acc[p][o] = fmaf(dwv[p], wpv, acc[p][o]);
        }
    }

    float* dst = g_agg + ((size_t)b * OC3 + g * 8) * HW + (y0 + py0) * 64 + x0 + px;
    #pragma unroll
    for (int o = 0; o < 8; o++)
        #pragma unroll
        for (int p = 0; p < 4; p++)
            dst[(size_t)o * HW + p * 64] = acc[p][o];
}

// ---------------------------------------------------------------------------
// K3: kv reduction (unchanged)
// ---------------------------------------------------------------------------
__global__ __launch_bounds__(256) void kv_k()
{
    int bh = blockIdx.x;
    int b = bh >> 6, h = bh & 63;
    const float* base = (h < 32 ? g_qkv : g_agg) + ((size_t)b * OC3 + (h & 31) * 24) * HW;
    const float* kp = base + 8 * HW;
    const float* vp = base + 16 * HW;

    float acc[8][9] = {};
    for (int n = threadIdx.x; n < HW; n += 256) {
        float kr[8], vr[8];
        #pragma unroll
        for (int d = 0; d < 8; d++) {
            kr[d] = fmaxf(kp[(size_t)d * HW + n], 0.f);
            vr[d] = vp[(size_t)d * HW + n];
        }
        #pragma unroll
        for (int d = 0; d < 8; d++) {
            #pragma unroll
            for (int e = 0; e < 8; e++) acc[d][e] = fmaf(kr[d], vr[e], acc[d][e]);
            acc[d][8] += kr[d];
        }
    }
    __shared__ float sred[8][72];
    int w = threadIdx.x >> 5, lane = threadIdx.x & 31;
    #pragma unroll
    for (int d = 0; d < 8; d++)
        #pragma unroll
        for (int e = 0; e < 9; e++) {
            float v = acc[d][e];
            #pragma unroll
            for (int o = 16; o > 0; o >>= 1) v += __shfl_down_sync(0xffffffffu, v, o);
            if (lane == 0) sred[w][d * 9 + e] = v;
        }
    __syncthreads();
    if (threadIdx.x < 72) {
        float v = 0.f;
        #pragma unroll
        for (int w2 = 0; w2 < 8; w2++) v += sred[w2][threadIdx.x];
        g_kv[(size_t)bh * 72 + threadIdx.x] = v;
    }
}

// ---------------------------------------------------------------------------
// K4 (HMMA): fused attention + proj GEMM + BN + residual. (unchanged from R9)
// ---------------------------------------------------------------------------
#define K4_WOFF  18432
#define K4_WST   36864
#define K4_AOFF  (18432 + 2 * K4_WST)          // 92160
#define K4_AST   34816
#define K4_ALO2  17408
#define K4_SMEM  (K4_AOFF + 2 * K4_AST)        // 161792

__global__ __launch_bounds__(512) void att_proj_mma_k(
    const float* __restrict__ x, const float* __restrict__ gamma,
    const float* __restrict__ beta, const float* __restrict__ mean,
    const float* __restrict__ var, float* __restrict__ out)
{
    extern __shared__ char smc[];
    float* kv_s = (float*)smc;
    uint32_t sb = smem_u32(smc);

    int tid = threadIdx.x, lane = tid & 31, wrp = tid >> 5;
    int b = blockIdx.z, n0 = blockIdx.x * 128, m0 = blockIdx.y * 128;
    int wm = (wrp >> 2) * 32, wn = (wrp & 3) * 32;
    int nl = tid & 127, hslot = tid >> 7;     // 0..3

    for (int i = tid; i < 4608; i += 512) kv_s[i] = g_kv[(size_t)b * 4608 + i];

    float acc[2][4][4] = {};

    auto stageW = [&](int hc, int s) {
        uint32_t d = sb + K4_WOFF + s * K4_WST;
        #pragma unroll
        for (int i = 0; i < 2; i++) {
            int c = i * 512 + tid;
            int row = c >> 3, seg = c & 7;
            size_t so = (size_t)(m0 + row) * 512 + hc * 64 + seg * 8;
            uint32_t dd = d + row * 144 + seg * 16;
            cpa16(dd, g_wphi + so);
            cpa16(dd + 18432, g_wplo + so);
        }
    };

    float qr[2][8];
    auto preloadQ = [&](int hc) {
        #pragma unroll
        for (int i = 0; i < 2; i++) {
            int h = hc * 8 + hslot + i * 4;
            const float* src = (h < 32 ? g_qkv : g_agg)
                             + ((size_t)b * OC3 + (h & 31) * 24) * HW + n0 + nl;
            #pragma unroll
            for (int d = 0; d < 8; d++) qr[i][d] = fmaxf(src[(size_t)d * HW], 0.f);
        }
    };

    stageW(0, 0); CP_COMMIT();
    preloadQ(0);
    __syncthreads();          // kv_s ready

    for (int hc = 0; hc < 8; hc++) {
        CP_WAIT0();
        __syncthreads();      // W(hc) visible; all MMA(hc-1) done
        if (hc < 7) { stageW(hc + 1, (hc + 1) & 1); CP_COMMIT(); }

        __nv_bfloat16* aHiP = (__nv_bfloat16*)(smc + K4_AOFF + (hc & 1) * K4_AST);
        __nv_bfloat16* aLoP = aHiP + 8704;      // +17408 B
        #pragma unroll
        for (int i = 0; i < 2; i++) {
            int hl = hslot + i * 4;
            int h = hc * 8 + hl;
            const float* kvh = kv_s + h * 72;
            float den = 0.f;
            #pragma unroll
            for (int d = 0; d < 8; d++) den = fmaf(qr[i][d], kvh[d * 9 + 8], den);
            float inv = 1.f / (den + 1e-15f);
            #pragma unroll
            for (int e = 0; e < 8; e++) {
                float s = 0.f;
                #pragma unroll
                for (int d = 0; d < 8; d++) s = fmaf(qr[i][d], kvh[d * 9 + e], s);
                s *= inv;
                __nv_bfloat16 hbv = __float2bfloat16(s);
                __nv_bfloat16 lbv = __float2bfloat16(s - __bfloat162float(hbv));
                int row = hl * 8 + e;
                aHiP[row * 136 + nl] = hbv;
                aLoP[row * 136 + nl] = lbv;
            }
        }
        if (hc < 7) preloadQ(hc + 1);           // global loads behind MMA
        __syncthreads();                        // att ready

        uint32_t wBase = sb + K4_WOFF + (hc & 1) * K4_WST;
        uint32_t bBase = sb + K4_AOFF + (hc & 1) * K4_AST;
        #pragma unroll
        for (int pass = 0; pass < 3; pass++) {
            uint32_t aB = wBase + ((pass == 2) ? 18432 : 0);
            uint32_t bB = bBase + ((pass == 1) ? K4_ALO2 : 0);
            #pragma unroll
            for (int ks = 0; ks < 4; ks++) {
                uint32_t af[2][4], bf[4][2];
                #pragma unroll
                for (int mi = 0; mi < 2; mi++)
                    ldsm_x4(af[mi][0], af[mi][1], af[mi][2], af[mi][3],
                        aB + (uint32_t)((wm + mi * 16 + (lane & 15)) * 144
                                        + (ks * 16 + (lane >> 4) * 8) * 2));
                #pragma unroll
                for (int ni = 0; ni < 4; ni++)
                    ldsm_x2t(bf[ni][0], bf[ni][1],
                        bB + (uint32_t)((ks * 16 + (lane & 15)) * 272
                                        + (wn + ni * 8) * 2));
                #pragma unroll
                for (int mi = 0; mi < 2; mi++)
                    #pragma unroll
                    for (int ni = 0; ni < 4; ni++)
                        mma_bf16(acc[mi][ni][0], acc[mi][ni][1],
                                 acc[mi][ni][2], acc[mi][ni][3],
                                 af[mi][0], af[mi][1], af[mi][2], af[mi][3],
                                 bf[ni][0], bf[ni][1]);
            }
        }
    }

    #pragma unroll
    for (int mi = 0; mi < 2; mi++) {
        #pragma unroll
        for (int half = 0; half < 2; half++) {
            int o = m0 + wm + mi * 16 + (lane >> 2) + half * 8;
            float invg = gamma[o] / sqrtf(var[o] + 1e-6f);
            float bias = beta[o] - mean[o] * invg;
            #pragma unroll
            for (int ni = 0; ni < 4; ni++) {
                int n = n0 + wn + ni * 8 + (lane & 3) * 2;
                size_t off = ((size_t)b * C_ + o) * HW + n;
                float2 xv = *(const float2*)(x + off);
                float2 r;
                r.x = xv.x + acc[mi][ni][half * 2 + 0] * invg + bias;
                r.y = xv.y + acc[mi][ni][half * 2 + 1] * invg + bias;
                *(float2*)(out + off) = r;
            }
        }
    }
}

// ---------------------------------------------------------------------------
extern "C" void kernel_launch(void* const* d_in, const int* in_sizes, int n_in,
                              void* d_out, int out_size)
{
    const float* x     = (const float*)d_in[0];
    const float* wqkv  = (const float*)d_in[1];
    const float* wdw   = (const float*)d_in[2];
    const float* wpw   = (const float*)d_in[3];
    const float* wproj = (const float*)d_in[4];
    const float* gamma = (const float*)d_in[5];
    const float* beta  = (const float*)d_in[6];
    const float* mean  = (const float*)d_in[7];
    const float* var   = (const float*)d_in[8];
    float* out = (float*)d_out;

    conv_x_k<<<8192, 256>>>(x);
    conv_w_k<<<320, 256>>>(wqkv, wproj);

    cudaFuncSetAttribute(qkv_mma_k, cudaFuncAttributeMaxDynamicSharedMemorySize, K1_SMEM);
    qkv_mma_k<<<dim3(32, 6, 8), 512, K1_SMEM>>>();

    dw_agg_k<<<dim3(2, 2, B_ * GRPS), 256>>>(wdw, wpw);
    kv_k<<<B_ * 64, 256>>>();

    cudaFuncSetAttribute(att_proj_mma_k, cudaFuncAttributeMaxDynamicSharedMemorySize, K4_SMEM);
    att_proj_mma_k<<<dim3(32, 2, B_), 512, K4_SMEM>>>(x, gamma, beta, mean, var, out);
}